// round 12
// baseline (speedup 1.0000x reference)
#include <cuda_runtime.h>
#include <cuda_fp16.h>

// Problem constants: N=100000, E=1600000, IN_C=16, HID=32, HEADS=2
#define MAXN 100000
#define MAXE 1600000
#define NEG 0.2f
#define INV_TEMP (1.0f / 0.7f)

// ---- device scratch (static; no allocations allowed; zero-init at load) ----
__device__ __align__(16) __half g_xp[MAXN * 64];   // [N][64] projected features (fp16)
__device__ float g_asrc[MAXN * 2];                 // attention src logits per head
__device__ float g_adst[MAXN * 2];                 // attention dst logits per head
__device__ __align__(16) __half g_ps[MAXN * 32];   // h @ w1[0:32,:]  (fp16)
__device__ __align__(16) __half g_pd[MAXN * 32];   // h @ w1[32:64,:] (fp16)
__device__ __align__(16) int2 g_edge[MAXE];        // packed (src, dst)
__device__ __align__(16) int g_rank[MAXE];         // rank of edge within its dst group
__device__ __align__(16) int g_srcs[MAXE];         // CSR: src ids grouped by dst
__device__ int g_deg[MAXN];                        // in-degree histogram (re-zeroed by scan)
__device__ int g_off[MAXN + 1];                    // CSR offsets
__device__ int g_bsum[128];                        // scan block totals
__device__ int g_bflag[128];                       // scan publish flags
__device__ int g_done;                             // scan->scatter barrier counter
__device__ int g_is64;

// K_init: tiny single-block kernel: zero scan flags + barrier counter; detect
// edge int width. (g_deg is zero at load and re-zeroed by k_scan each call.)
__global__ void k_init(const int* __restrict__ ei_words) {
    int t = threadIdx.x;
    g_bflag[t] = 0;
    if (t == 0) {
        g_done = 0;
        int nonzero = 0;
        #pragma unroll
        for (int j = 0; j < 64; j++)
            if (ei_words[2 * j + 1] != 0) nonzero++;
        g_is64 = (nonzero == 0) ? 1 : 0;
    }
}

// K_pack_node: blocks [0, nodeBlocks) do the node projection (chunked,
// low-reg); remaining blocks pack edges + histogram + per-dst rank.
__global__ void __launch_bounds__(256, 4) k_pack_node(
    const void* __restrict__ ei,
    const float* __restrict__ x, const float* __restrict__ W,
    const float* __restrict__ att_src, const float* __restrict__ att_dst,
    int N, int E, int nodeBlocks) {
    int tid = threadIdx.x;

    if (blockIdx.x >= (unsigned)nodeBlocks) {
        // ---- edge pack part ----
        int e = (blockIdx.x - nodeBlocks) * blockDim.x + tid;
        if (e >= E) return;
        int s, d;
        if (g_is64) {
            const long long* p = (const long long*)ei;
            s = (int)p[e];
            d = (int)p[e + E];
        } else {
            const int* p = (const int*)ei;
            s = p[e];
            d = p[e + E];
        }
        g_edge[e] = make_int2(s, d);
        g_rank[e] = atomicAdd(&g_deg[d], 1);
        return;
    }

    // ---- node projection part (chunked, 16 output columns at a time) ----
    __shared__ float sW[16 * 64];
    __shared__ float sAs[64];
    __shared__ float sAd[64];
    for (int i = tid; i < 16 * 64; i += blockDim.x) sW[i] = W[i];
    if (tid < 64) { sAs[tid] = att_src[tid]; sAd[tid] = att_dst[tid]; }
    __syncthreads();

    int n = blockIdx.x * blockDim.x + tid;
    if (n >= N) return;

    float xv[16];
    const float4* x4 = (const float4*)(x + (size_t)n * 16);
    #pragma unroll
    for (int i = 0; i < 4; i++) {
        float4 t = x4[i];
        xv[4 * i + 0] = t.x; xv[4 * i + 1] = t.y;
        xv[4 * i + 2] = t.z; xv[4 * i + 3] = t.w;
    }

    float hs[2] = {0.f, 0.f};
    float hd[2] = {0.f, 0.f};
    uint4* xpo = (uint4*)(g_xp + (size_t)n * 64);

    #pragma unroll
    for (int ch = 0; ch < 4; ch++) {
        float v[16];
        float as = 0.f, ad = 0.f;
        #pragma unroll
        for (int jj = 0; jj < 16; jj++) {
            int j = ch * 16 + jj;
            float acc = 0.f;
            #pragma unroll
            for (int k = 0; k < 16; k++) acc = fmaf(xv[k], sW[k * 64 + j], acc);
            v[jj] = acc;
            as = fmaf(sAs[j], acc, as);
            ad = fmaf(sAd[j], acc, ad);
        }
        int hh = ch >> 1;
        hs[hh] += as;
        hd[hh] += ad;
        union { uint4 u; __half2 p[4]; } pk;
        #pragma unroll
        for (int g = 0; g < 2; g++) {
            #pragma unroll
            for (int j = 0; j < 4; j++)
                pk.p[j] = __floats2half2_rn(v[8 * g + 2 * j], v[8 * g + 2 * j + 1]);
            xpo[2 * ch + g] = pk.u;
        }
    }

    g_asrc[n * 2 + 0] = hs[0]; g_asrc[n * 2 + 1] = hs[1];
    g_adst[n * 2 + 0] = hd[0]; g_adst[n * 2 + 1] = hd[1];
}

// K_scan_scatter: one kernel, two phases.
// Phase 1: exclusive scan of g_deg -> g_off via warp-shuffle block scan +
//   parallel lookback (98 blocks, all co-resident). Re-zeroes g_deg for the
//   next call. Device-wide flag barrier (same residency guarantee as lookback).
// Phase 2: grid-stride atomic-free scatter: g_srcs[g_off[d] + rank] = src.
__global__ void __launch_bounds__(1024) k_scan_scatter(int N, int E, int NB) {
    __shared__ int warpsums[32];
    __shared__ int sred[32];
    __shared__ int sbase;
    const unsigned FULL = 0xFFFFFFFFu;
    int tid = threadIdx.x;
    int lane = tid & 31, wid = tid >> 5;
    int b = blockIdx.x;
    int i = b * 1024 + tid;

    // ---- phase 1: scan ----
    int v = (i < N) ? g_deg[i] : 0;
    if (i < N) g_deg[i] = 0;                 // restore invariant for next call
    int sc = v;
    #pragma unroll
    for (int ofs = 1; ofs < 32; ofs <<= 1) {
        int t = __shfl_up_sync(FULL, sc, ofs);
        if (lane >= ofs) sc += t;
    }
    if (lane == 31) warpsums[wid] = sc;
    __syncthreads();
    if (wid == 0) {
        int w = warpsums[lane];
        #pragma unroll
        for (int ofs = 1; ofs < 32; ofs <<= 1) {
            int t = __shfl_up_sync(FULL, w, ofs);
            if (lane >= ofs) w += t;
        }
        warpsums[lane] = w;
    }
    __syncthreads();
    int blockpref = (wid > 0) ? warpsums[wid - 1] : 0;
    int excl = sc + blockpref - v;
    int total = warpsums[31];

    if (tid == 0) {
        g_bsum[b] = total;
        __threadfence();
        atomicExch(&g_bflag[b], 1);
    }

    int part = 0;
    if (tid < b) {
        while (atomicAdd(&g_bflag[tid], 0) == 0) { }
        __threadfence();
        part = g_bsum[tid];
    }
    #pragma unroll
    for (int ofs = 16; ofs > 0; ofs >>= 1)
        part += __shfl_xor_sync(FULL, part, ofs);
    if (lane == 0) sred[wid] = part;
    __syncthreads();
    if (tid == 0) {
        int s = 0;
        #pragma unroll
        for (int k = 0; k < 4; k++) s += sred[k];
        sbase = s;
    }
    __syncthreads();

    if (i < N) g_off[i] = excl + sbase;
    if (b == 0 && tid == 0) g_off[N] = E;

    // ---- device-wide barrier (all NB blocks co-resident) ----
    __threadfence();
    __syncthreads();
    if (tid == 0) atomicAdd(&g_done, 1);
    if (tid == 0) {
        while (atomicAdd(&g_done, 0) < NB) { }
    }
    __syncthreads();
    __threadfence();

    // ---- phase 2: scatter (grid-stride, ~16 independent edges/thread) ----
    int S = NB * 1024;
    int gtid = b * 1024 + tid;
    int e = gtid;
    for (; e + 3 * S < E; e += 4 * S) {
        int2 sd0 = g_edge[e];
        int2 sd1 = g_edge[e + S];
        int2 sd2 = g_edge[e + 2 * S];
        int2 sd3 = g_edge[e + 3 * S];
        int r0 = g_rank[e];
        int r1 = g_rank[e + S];
        int r2 = g_rank[e + 2 * S];
        int r3 = g_rank[e + 3 * S];
        int o0 = __ldg(&g_off[sd0.y]);
        int o1 = __ldg(&g_off[sd1.y]);
        int o2 = __ldg(&g_off[sd2.y]);
        int o3 = __ldg(&g_off[sd3.y]);
        g_srcs[o0 + r0] = sd0.x;
        g_srcs[o1 + r1] = sd1.x;
        g_srcs[o2 + r2] = sd2.x;
        g_srcs[o3 + r3] = sd3.x;
    }
    for (; e < E; e += S) {
        int2 sd = g_edge[e];
        g_srcs[__ldg(&g_off[sd.y]) + g_rank[e]] = sd.x;
    }
}

// K2b3: warp-per-destination GAT aggregation + fused MLP layer-1 fold.
__global__ void __launch_bounds__(256) k2b3_aggregate(const float* __restrict__ bias,
                                                      const float* __restrict__ w1, int N) {
    __shared__ float sW1[64 * 32];
    int tid = threadIdx.x;
    for (int i = tid; i < 64 * 32; i += blockDim.x) sW1[i] = w1[i];
    __syncthreads();

    int n = (blockIdx.x * blockDim.x + tid) >> 5;
    if (n >= N) return;
    int c = tid & 31;
    int h = c >> 4;
    const unsigned FULL = 0xFFFFFFFFu;

    float adn = g_adst[n * 2 + h];
    float ee = g_asrc[n * 2 + h] + adn;           // self loop
    ee = ee > 0.f ? ee : NEG * ee;
    float w = __expf(ee);
    float2 xs = __half22float2(*(const __half2*)(g_xp + (size_t)n * 64 + 2 * c));
    float acc0 = w * xs.x, acc1 = w * xs.y, dsum = w;

    int i = g_off[n];
    int end = g_off[n + 1];

    for (; i + 8 <= end; i += 8) {
        int s[8];
        #pragma unroll
        for (int j = 0; j < 8; j++) s[j] = __ldg(&g_srcs[i + j]);
        float a[8];
        __half2 xh[8];
        #pragma unroll
        for (int j = 0; j < 8; j++) {
            a[j] = __ldg(&g_asrc[s[j] * 2 + h]);
            xh[j] = *(const __half2*)(g_xp + (size_t)s[j] * 64 + 2 * c);
        }
        #pragma unroll
        for (int j = 0; j < 8; j++) {
            float e0 = a[j] + adn; e0 = e0 > 0.f ? e0 : NEG * e0;
            float w0 = __expf(e0);
            dsum += w0;
            float2 f = __half22float2(xh[j]);
            acc0 = fmaf(w0, f.x, acc0);
            acc1 = fmaf(w0, f.y, acc1);
        }
    }
    for (; i + 2 <= end; i += 2) {
        int s0 = __ldg(&g_srcs[i]), s1 = __ldg(&g_srcs[i + 1]);
        float a0 = __ldg(&g_asrc[s0 * 2 + h]);
        float a1 = __ldg(&g_asrc[s1 * 2 + h]);
        __half2 x0 = *(const __half2*)(g_xp + (size_t)s0 * 64 + 2 * c);
        __half2 x1 = *(const __half2*)(g_xp + (size_t)s1 * 64 + 2 * c);
        float e0 = a0 + adn; e0 = e0 > 0.f ? e0 : NEG * e0;
        float e1 = a1 + adn; e1 = e1 > 0.f ? e1 : NEG * e1;
        float w0 = __expf(e0), w1v = __expf(e1);
        dsum += w0 + w1v;
        float2 f0 = __half22float2(x0);
        float2 f1 = __half22float2(x1);
        acc0 = fmaf(w0, f0.x, acc0);  acc1 = fmaf(w0, f0.y, acc1);
        acc0 = fmaf(w1v, f1.x, acc0); acc1 = fmaf(w1v, f1.y, acc1);
    }
    if (i < end) {
        int s = __ldg(&g_srcs[i]);
        float a = __ldg(&g_asrc[s * 2 + h]);
        __half2 xh = *(const __half2*)(g_xp + (size_t)s * 64 + 2 * c);
        float e0 = a + adn; e0 = e0 > 0.f ? e0 : NEG * e0;
        float w0 = __expf(e0);
        dsum += w0;
        float2 f = __half22float2(xh);
        acc0 = fmaf(w0, f.x, acc0);
        acc1 = fmaf(w0, f.y, acc1);
    }

    float d0 = __shfl_sync(FULL, dsum, 0);
    float d1 = __shfl_sync(FULL, dsum, 16);
    float p0 = __shfl_sync(FULL, acc0, (c + 16) & 31);
    float p1 = __shfl_sync(FULL, acc1, (c + 16) & 31);

    int c15 = c & 15;
    float h0 = 0.5f * (acc0 / d0 + p0 / d1) + __ldg(&bias[2 * c15]);
    float h1 = 0.5f * (acc1 / d0 + p1 / d1) + __ldg(&bias[2 * c15 + 1]);

    // fused k3: ps/pd = h @ w1 (lane c computes output channel c)
    float ps = 0.f, pd = 0.f;
    #pragma unroll
    for (int k = 0; k < 16; k++) {
        float ha = __shfl_sync(FULL, h0, k);
        float hb = __shfl_sync(FULL, h1, k);
        ps = fmaf(ha, sW1[(2 * k) * 32 + c], ps);
        ps = fmaf(hb, sW1[(2 * k + 1) * 32 + c], ps);
        pd = fmaf(ha, sW1[(32 + 2 * k) * 32 + c], pd);
        pd = fmaf(hb, sW1[(32 + 2 * k + 1) * 32 + c], pd);
    }
    g_ps[(size_t)n * 32 + c] = __float2half_rn(ps);
    g_pd[(size_t)n * 32 + c] = __float2half_rn(pd);
}

// K4: per-edge MLP. 4-lane group per consecutive edge pair (one int4 edge
// load); two independent pairs in flight per thread. ps+pd summed in half2.
__device__ __forceinline__ float mlp_quarter(const uint4 a, const uint4 b,
                                             const float* b1r, const float* w2r) {
    union { uint4 u; __half2 hh[4]; } ua, ub;
    ua.u = a; ub.u = b;
    float acc = 0.f;
    #pragma unroll
    for (int j = 0; j < 4; j++) {
        __half2 s = __hadd2(ua.hh[j], ub.hh[j]);
        float2 f = __half22float2(s);
        float h0 = fmaxf(f.x + b1r[2 * j], 0.f);
        float h1 = fmaxf(f.y + b1r[2 * j + 1], 0.f);
        acc = fmaf(h0, w2r[2 * j], acc);
        acc = fmaf(h1, w2r[2 * j + 1], acc);
    }
    return acc;
}

__global__ void __launch_bounds__(256) k4_edge_mlp(const float* __restrict__ b1,
                                                   const float* __restrict__ w2,
                                                   const float* __restrict__ b2,
                                                   float* __restrict__ out, int E) {
    int tid = blockIdx.x * blockDim.x + threadIdx.x;
    int q = tid & 3;
    float b1r[8], w2r[8];
    #pragma unroll
    for (int i = 0; i < 8; i++) {
        b1r[i] = __ldg(&b1[q * 8 + i]);
        w2r[i] = __ldg(&w2[q * 8 + i]);
    }
    float b2v = __ldg(&b2[0]);
    const unsigned FULL = 0xFFFFFFFFu;

    int nGroups = (gridDim.x * blockDim.x) >> 2;
    int nPairs = (E + 1) >> 1;

    for (int p = tid >> 2; p < nPairs; p += 2 * nGroups) {
        int pB = p + nGroups;
        bool hasB = pB < nPairs;
        int eA = 2 * p, eB = 2 * pB;

        int4 edA = __ldg((const int4*)(g_edge + eA));
        int4 edB = hasB ? __ldg((const int4*)(g_edge + eB)) : make_int4(0, 0, 0, 0);

        uint4 psA0 = *((const uint4*)(g_ps + (size_t)edA.x * 32) + q);
        uint4 pdA0 = *((const uint4*)(g_pd + (size_t)edA.y * 32) + q);
        uint4 psA1 = *((const uint4*)(g_ps + (size_t)edA.z * 32) + q);
        uint4 pdA1 = *((const uint4*)(g_pd + (size_t)edA.w * 32) + q);
        uint4 psB0 = *((const uint4*)(g_ps + (size_t)edB.x * 32) + q);
        uint4 pdB0 = *((const uint4*)(g_pd + (size_t)edB.y * 32) + q);
        uint4 psB1 = *((const uint4*)(g_ps + (size_t)edB.z * 32) + q);
        uint4 pdB1 = *((const uint4*)(g_pd + (size_t)edB.w * 32) + q);

        float vA0 = mlp_quarter(psA0, pdA0, b1r, w2r);
        float vA1 = mlp_quarter(psA1, pdA1, b1r, w2r);
        float vB0 = mlp_quarter(psB0, pdB0, b1r, w2r);
        float vB1 = mlp_quarter(psB1, pdB1, b1r, w2r);

        float a0 = vA0 + __shfl_xor_sync(FULL, vA0, 1);
        float a1 = vA1 + __shfl_xor_sync(FULL, vA1, 1);
        float mA = (q & 1) ? a1 : a0;
        mA += __shfl_xor_sync(FULL, mA, 2);

        float c0 = vB0 + __shfl_xor_sync(FULL, vB0, 1);
        float c1 = vB1 + __shfl_xor_sync(FULL, vB1, 1);
        float mB = (q & 1) ? c1 : c0;
        mB += __shfl_xor_sync(FULL, mB, 2);

        if (q < 2) {
            int e = eA + q;
            if (e < E) out[e] = (mA + b2v) * INV_TEMP;
            if (hasB) {
                int e2 = eB + q;
                if (e2 < E) out[e2] = (mB + b2v) * INV_TEMP;
            }
        }
    }
}

extern "C" void kernel_launch(void* const* d_in, const int* in_sizes, int n_in,
                              void* d_out, int out_size) {
    const float* x        = (const float*)d_in[0];
    const void*  ei       = d_in[1];
    const float* W        = (const float*)d_in[2];
    const float* att_src  = (const float*)d_in[3];
    const float* att_dst  = (const float*)d_in[4];
    const float* bias     = (const float*)d_in[5];
    const float* w1       = (const float*)d_in[6];
    const float* b1       = (const float*)d_in[7];
    const float* w2       = (const float*)d_in[8];
    const float* b2       = (const float*)d_in[9];
    float* out = (float*)d_out;

    int N = in_sizes[0] / 16;  // x is [N, 16]
    int E = in_sizes[1] / 2;   // edge_index is [2, E]
    int NB = (N + 1023) / 1024;          // 98 blocks <= 148 SMs (co-resident)
    int nodeBlocks = (N + 255) / 256;
    int packBlocks = (E + 255) / 256;

    k_init<<<1, 128>>>((const int*)ei);
    k_pack_node<<<nodeBlocks + packBlocks, 256>>>(ei, x, W, att_src, att_dst,
                                                  N, E, nodeBlocks);
    k_scan_scatter<<<NB, 1024>>>(N, E, NB);
    {
        long long T = (long long)N * 32;
        k2b3_aggregate<<<(unsigned)((T + 255) / 256), 256>>>(bias, w1, N);
    }
    k4_edge_mlp<<<1184, 256>>>(b1, w2, b2, out, E);
}